// round 12
// baseline (speedup 1.0000x reference)
#include <cuda_runtime.h>
#include <cuda_bf16.h>
#include <math_constants.h>

// Problem constants
#define BATCH 8
#define HH 56
#define WW 56
#define CC 256
#define NPIX (BATCH*HH*WW)        // 25088
#define NH 8
#define HD 32
#define NWIN 7
#define NREG 49
#define RS 8                      // region side
#define S_TOK 64                  // tokens per region
#define TOPK 4
#define TS 256                    // TOPK * S_TOK
#define K2 32                     // token top-k

#define FULLMASK 0xffffffffu

// ------------------------- scratch (device globals; no allocation) -----------
__device__ float g_qkv[NPIX * 768];     // (pixel, 768) : q | k | v  (~77MB)
__device__ float g_ao [NPIX * CC];      // attention out (+lepe), NHWC (~26MB)
__device__ float g_qr [BATCH * NREG * CC];
__device__ float g_kr [BATCH * NREG * CC];
__device__ int   g_idx[BATCH * NREG * TOPK];

// ------------------------- tf32-split tensor-core GEMM -----------------------
// C = A @ W^T + bias.  A:[M x K] row-major (lda), W:[N x K] row-major, C:[M x ldc].
// fp32 emulated as tf32 hi/lo split, 3 mma terms (hh + hl + lh), err ~2^-21.
// BM=128, BN=64, BK=16; 256 threads = 8 warps; warp w owns rows [w*16, w*16+16).
// mma.sync.aligned.m16n8k8.row.col.f32.tf32.tf32.f32
#define GM 128
#define GN 64
#define GK 16

__device__ __forceinline__ void tf32_split(float x, unsigned& h, unsigned& l) {
    unsigned hb;
    asm("cvt.rna.tf32.f32 %0, %1;" : "=r"(hb) : "f"(x));
    float r = x - __uint_as_float(hb);
    unsigned lb;
    asm("cvt.rna.tf32.f32 %0, %1;" : "=r"(lb) : "f"(r));
    h = hb; l = lb;
}

#define MMA_TF32(C0,C1,C2,C3, A0,A1,A2,A3, B0,B1)                         \
    asm volatile(                                                         \
        "mma.sync.aligned.m16n8k8.row.col.f32.tf32.tf32.f32 "             \
        "{%0,%1,%2,%3}, {%4,%5,%6,%7}, {%8,%9}, {%0,%1,%2,%3};"           \
        : "+f"(C0), "+f"(C1), "+f"(C2), "+f"(C3)                          \
        : "r"(A0), "r"(A1), "r"(A2), "r"(A3), "r"(B0), "r"(B1))

__global__ __launch_bounds__(256)
void gemm_tf32_kernel(const float* __restrict__ A, int lda,
                      const float* __restrict__ W,
                      const float* __restrict__ bias,
                      float* __restrict__ C, int ldc,
                      int K)
{
    // pads: fragment LDS bank = (tig*8 + g) mod 32 -> conflict-free
    __shared__ float Ah[GK][136], Al[GK][136];
    __shared__ float Bh[GK][72],  Bl[GK][72];

    const int tid  = threadIdx.x;
    const int row0 = blockIdx.y * GM;
    const int col0 = blockIdx.x * GN;
    const int lane = tid & 31, wrp = tid >> 5;
    const int g    = lane >> 2;       // groupID (0..7)
    const int tig  = lane & 3;        // thread-in-group (0..3)
    const int w16  = wrp * 16;

    float acc[8][4];
#pragma unroll
    for (int j = 0; j < 8; j++)
#pragma unroll
        for (int c = 0; c < 4; c++) acc[j][c] = 0.f;

    // loader indices: A tile 128x16 = 512 float4 (2/thread); B tile 64x16 = 256 (1/thread)
    const int ia0 = tid * 2,      ra0 = ia0 >> 2, ca0 = ia0 & 3;
    const int ia1 = tid * 2 + 1,  ra1 = ia1 >> 2, ca1 = ia1 & 3;
    const int rb  = tid >> 2,     cb  = tid & 3;

    for (int k0 = 0; k0 < K; k0 += GK) {
        // global loads first (overlap with previous chunk's compute drain)
        float4 av0 = *(const float4*)&A[(long)(row0 + ra0) * lda + k0 + ca0 * 4];
        float4 av1 = *(const float4*)&A[(long)(row0 + ra1) * lda + k0 + ca1 * 4];
        float4 bv  = *(const float4*)&W[(long)(col0 + rb)  * K   + k0 + cb  * 4];

        __syncthreads();   // previous chunk fully consumed

        // convert + store transposed (k-major)
        {
            float xs[4] = {av0.x, av0.y, av0.z, av0.w};
#pragma unroll
            for (int u = 0; u < 4; u++) {
                unsigned h, l; tf32_split(xs[u], h, l);
                Ah[ca0*4+u][ra0] = __uint_as_float(h);
                Al[ca0*4+u][ra0] = __uint_as_float(l);
            }
            float ys[4] = {av1.x, av1.y, av1.z, av1.w};
#pragma unroll
            for (int u = 0; u < 4; u++) {
                unsigned h, l; tf32_split(ys[u], h, l);
                Ah[ca1*4+u][ra1] = __uint_as_float(h);
                Al[ca1*4+u][ra1] = __uint_as_float(l);
            }
            float zs[4] = {bv.x, bv.y, bv.z, bv.w};
#pragma unroll
            for (int u = 0; u < 4; u++) {
                unsigned h, l; tf32_split(zs[u], h, l);
                Bh[cb*4+u][rb] = __uint_as_float(h);
                Bl[cb*4+u][rb] = __uint_as_float(l);
            }
        }
        __syncthreads();

        // two k8 steps per chunk
#pragma unroll
        for (int ks = 0; ks < 2; ks++) {
            const int kk = ks * 8;
            unsigned ah0 = __float_as_uint(Ah[kk+tig  ][w16+g]);
            unsigned ah1 = __float_as_uint(Ah[kk+tig  ][w16+g+8]);
            unsigned ah2 = __float_as_uint(Ah[kk+tig+4][w16+g]);
            unsigned ah3 = __float_as_uint(Ah[kk+tig+4][w16+g+8]);
            unsigned al0 = __float_as_uint(Al[kk+tig  ][w16+g]);
            unsigned al1 = __float_as_uint(Al[kk+tig  ][w16+g+8]);
            unsigned al2 = __float_as_uint(Al[kk+tig+4][w16+g]);
            unsigned al3 = __float_as_uint(Al[kk+tig+4][w16+g+8]);
#pragma unroll
            for (int j = 0; j < 8; j++) {
                unsigned bh0 = __float_as_uint(Bh[kk+tig  ][j*8+g]);
                unsigned bh1 = __float_as_uint(Bh[kk+tig+4][j*8+g]);
                unsigned bl0 = __float_as_uint(Bl[kk+tig  ][j*8+g]);
                unsigned bl1 = __float_as_uint(Bl[kk+tig+4][j*8+g]);
                MMA_TF32(acc[j][0],acc[j][1],acc[j][2],acc[j][3],
                         ah0,ah1,ah2,ah3, bh0,bh1);            // hi*hi
                MMA_TF32(acc[j][0],acc[j][1],acc[j][2],acc[j][3],
                         ah0,ah1,ah2,ah3, bl0,bl1);            // hi*lo
                MMA_TF32(acc[j][0],acc[j][1],acc[j][2],acc[j][3],
                         al0,al1,al2,al3, bh0,bh1);            // lo*hi
            }
        }
    }

    // epilogue: c0:(g, tig*2) c1:(g, tig*2+1) c2:(g+8, tig*2) c3:(g+8, tig*2+1)
    const int rowA = row0 + w16 + g;
    const int rowB = rowA + 8;
#pragma unroll
    for (int j = 0; j < 8; j++) {
        int cbase = col0 + j * 8 + tig * 2;
        float b0 = __ldg(&bias[cbase]);
        float b1 = __ldg(&bias[cbase + 1]);
        float2 o0 = make_float2(acc[j][0] + b0, acc[j][1] + b1);
        float2 o1 = make_float2(acc[j][2] + b0, acc[j][3] + b1);
        *(float2*)&C[(long)rowA * ldc + cbase] = o0;
        *(float2*)&C[(long)rowB * ldc + cbase] = o1;
    }
}

// ------------------------- region pooling (mean over 8x8) --------------------
__global__ void pool_kernel(const float* __restrict__ qkv,
                            float* __restrict__ qr, float* __restrict__ kr)
{
    int n = blockIdx.x, b = blockIdx.y, c = threadIdx.x;
    int h0 = (n / NWIN) * RS, w0 = (n % NWIN) * RS;
    float sq = 0.f, sk = 0.f;
#pragma unroll 8
    for (int p = 0; p < 64; p++) {
        long pix = (long)(b * HH + h0 + (p >> 3)) * WW + w0 + (p & 7);
        sq += qkv[pix * 768 + c];
        sk += qkv[pix * 768 + 256 + c];
    }
    qr[(b * NREG + n) * CC + c] = sq * 0.015625f;
    kr[(b * NREG + n) * CC + c] = sk * 0.015625f;
}

// ------------------------- region routing: a_r + top-4 -----------------------
__global__ void route_kernel(const float* __restrict__ qr,
                             const float* __restrict__ kr,
                             int* __restrict__ idxr)
{
    __shared__ float qrow[CC];
    __shared__ float ar[64];
    int i = blockIdx.x, b = blockIdx.y, tid = threadIdx.x;
    for (int c = tid; c < CC; c += 64) qrow[c] = qr[(b * NREG + i) * CC + c];
    if (tid >= NREG && tid < 64) ar[tid] = -CUDART_INF_F;
    __syncthreads();
    if (tid < NREG) {
        const float* krow = &kr[(b * NREG + tid) * CC];
        float acc = 0.f;
#pragma unroll 8
        for (int c = 0; c < CC; c++) acc += qrow[c] * krow[c];
        ar[tid] = acc;
    }
    __syncthreads();
    if (tid == 0) {
#pragma unroll
        for (int t = 0; t < TOPK; t++) {
            float best = -CUDART_INF_F; int bi = 0;
            for (int j = 0; j < NREG; j++)
                if (ar[j] > best) { best = ar[j]; bi = j; }
            ar[bi] = -CUDART_INF_F;
            idxr[(b * NREG + i) * TOPK + t] = bi;
        }
    }
}

// ------------------------- sparse attention (warp-autonomous) ----------------
#define KPAD 36
#define VPAD 33
#define ATTN_SMEM_FLOATS (256*KPAD + 256*VPAD)
#define ATTN_SMEM_BYTES  (ATTN_SMEM_FLOATS * 4)

__global__ __launch_bounds__(256)
void attn_kernel(const float* __restrict__ qkv,
                 const int* __restrict__ idxr,
                 const float* __restrict__ lw,
                 const float* __restrict__ lb,
                 float* __restrict__ ao)
{
    const int n = blockIdx.x, m = blockIdx.y, b = blockIdx.z;
    extern __shared__ float sm[];
    float* k_s = sm;                      // 256*36
    float* v_s = sm + 256 * KPAD;         // 256*33
    __shared__ float pairbuf[8][64];      // per-warp (w, idx) pairs

    const int tid  = threadIdx.x;
    const int lane = tid & 31, wrp = tid >> 5;
    const int h0 = (n / NWIN) * RS, w0 = (n % NWIN) * RS;
    const int ch = m * 32 + lane;

    // ---- load gathered K/V rows into shared (one token row per thread) ----
    {
        int r  = __ldg(&idxr[(b * NREG + n) * TOPK + (tid >> 6)]);
        int sp = tid & 63;
        int hi = (r / NWIN) * RS + (sp >> 3);
        int wi = (r % NWIN) * RS + (sp & 7);
        long base = (long)((b * HH + hi) * WW + wi) * 768;
        const float* kp = qkv + base + 256 + m * 32;
        const float* vp = qkv + base + 512 + m * 32;
#pragma unroll
        for (int d4 = 0; d4 < 8; d4++) {
            float4 kv = __ldg((const float4*)(kp + d4 * 4));
            float4 vv = __ldg((const float4*)(vp + d4 * 4));
            *(float4*)&k_s[tid * KPAD + d4 * 4] = kv;
            int o = tid * VPAD + d4 * 4;
            v_s[o]   = vv.x; v_s[o+1] = vv.y; v_s[o+2] = vv.z; v_s[o+3] = vv.w;
        }
    }

    // per-thread lepe weights/bias for channel ch
    float lwr[9];
#pragma unroll
    for (int i = 0; i < 9; i++) lwr[i] = __ldg(&lw[ch * 9 + i]);
    const float lbr = __ldg(&lb[ch]);

    __syncthreads();

    // ---- each warp processes rows wrp*8 .. wrp*8+7 as 4 pairs ----
    for (int pr = 0; pr < 4; pr++) {
        const int s0 = wrp * 8 + pr * 2;
        const int s1 = s0 + 1;
        const int hiA = h0 + (s0 >> 3), wiA = w0 + (s0 & 7);
        const int hiB = h0 + (s1 >> 3), wiB = w0 + (s1 & 7);
        const float* qA = qkv + (long)((b * HH + hiA) * WW + wiA) * 768 + m * 32;
        const float* qB = qkv + (long)((b * HH + hiB) * WW + wiB) * 768 + m * 32;

        float f0[8], f1[8];
#pragma unroll
        for (int i = 0; i < 8; i++) { f0[i] = 0.f; f1[i] = 0.f; }

#pragma unroll
        for (int d4 = 0; d4 < 8; d4++) {
            float4 qa = __ldg((const float4*)(qA + d4 * 4));
            float4 qb = __ldg((const float4*)(qB + d4 * 4));
#pragma unroll
            for (int i = 0; i < 8; i++) {
                float4 k4 = *(const float4*)&k_s[(lane + 32 * i) * KPAD + d4 * 4];
                f0[i] += qa.x*k4.x + qa.y*k4.y + qa.z*k4.z + qa.w*k4.w;
                f1[i] += qb.x*k4.x + qb.y*k4.y + qb.z*k4.z + qb.w*k4.w;
            }
        }
#pragma unroll
        for (int i = 0; i < 8; i++) { f0[i] *= 0.0625f; f1[i] *= 0.0625f; }

        // ---- per row: radix top-32, softmax, compaction, AV, lepe, store ----
#pragma unroll
        for (int rr = 0; rr < 2; rr++) {
            const float* f = rr ? f1 : f0;
            const int hi = rr ? hiB : hiA;
            const int wi = rr ? wiB : wiA;

            unsigned u[8];
#pragma unroll
            for (int i = 0; i < 8; i++) {
                unsigned t = __float_as_uint(f[i]);
                u[i] = (t & 0x80000000u) ? ~t : (t | 0x80000000u);
            }

            // 2-bit-per-step radix select: largest P with count(u >= P) >= 32
            unsigned P = 0;
            int cnt = 256;
            for (int bit = 30; bit >= 0; bit -= 2) {
                unsigned c1 = P | (1u << bit);
                unsigned c2 = P | (2u << bit);
                unsigned c3 = P | (3u << bit);
                int pk = 0;
#pragma unroll
                for (int i = 0; i < 8; i++) {
                    pk += (u[i] >= c1 ? 1 : 0)
                        + (u[i] >= c2 ? (1 << 10) : 0)
                        + (u[i] >= c3 ? (1 << 20) : 0);
                }
                pk = __reduce_add_sync(FULLMASK, pk);
                int n1 = pk & 1023, n2 = (pk >> 10) & 1023, n3 = pk >> 20;
                if (n3 >= 32)      { P = c3; cnt = n3; }
                else if (n2 >= 32) { P = c2; cnt = n2; }
                else if (n1 >= 32) { P = c1; cnt = n1; }
                if (cnt == 32) break;
            }
            float Tf = (P & 0x80000000u) ? __uint_as_float(P & 0x7fffffffu)
                                         : __uint_as_float(~P);

            // weights + compaction into pairbuf
            int base = 0;
#pragma unroll
            for (int i = 0; i < 8; i++) {
                bool sel = (u[i] >= P);
                unsigned bi = __ballot_sync(FULLMASK, sel);
                if (sel) {
                    int pos = base + __popc(bi & ((1u << lane) - 1u));
                    if (pos < 32) {
                        float wv = __expf(f[i] - Tf);
                        pairbuf[wrp][2*pos]   = wv;
                        pairbuf[wrp][2*pos+1] = __int_as_float(lane + 32 * i);
                    }
                }
                base += __popc(bi);
            }
            __syncwarp();

            // gather AV + lsum from the 32 compacted pairs
            float acc = 0.f, ls = 0.f;
#pragma unroll 4
            for (int j = 0; j < 32; j++) {
                float2 p = *(const float2*)&pairbuf[wrp][2*j];
                int idx = __float_as_int(p.y);
                acc += p.x * v_s[idx * VPAD + lane];
                ls  += p.x;
            }
            acc *= __frcp_rn(ls);
            __syncwarp();   // pairbuf reused next row

            // fused lepe: depthwise 3x3 on v at (hi, wi, ch)
            float lp = lbr;
#pragma unroll
            for (int dy = 0; dy < 3; dy++) {
                int h2 = hi + dy - 1;
                if ((unsigned)h2 >= (unsigned)HH) continue;
#pragma unroll
                for (int dx = 0; dx < 3; dx++) {
                    int w2 = wi + dx - 1;
                    if ((unsigned)w2 >= (unsigned)WW) continue;
                    lp += __ldg(&qkv[(long)((b * HH + h2) * WW + w2) * 768 + 512 + ch])
                        * lwr[dy * 3 + dx];
                }
            }

            long pix = (long)(b * HH + hi) * WW + wi;
            ao[pix * 256 + ch] = acc + lp;
        }
    }
}

// ------------------------- launch ---------------------------------------------
extern "C" void kernel_launch(void* const* d_in, const int* in_sizes, int n_in,
                              void* d_out, int out_size)
{
    const float* x      = (const float*)d_in[0];
    const float* qkv_w  = (const float*)d_in[1];
    const float* qkv_b  = (const float*)d_in[2];
    const float* lepe_w = (const float*)d_in[3];
    const float* lepe_b = (const float*)d_in[4];
    const float* out_w  = (const float*)d_in[5];
    const float* out_b  = (const float*)d_in[6];
    float* y = (float*)d_out;

    float *qkv_p, *ao_p, *qr_p, *kr_p; int* idx_p;
    cudaGetSymbolAddress((void**)&qkv_p, g_qkv);
    cudaGetSymbolAddress((void**)&ao_p,  g_ao);
    cudaGetSymbolAddress((void**)&qr_p,  g_qr);
    cudaGetSymbolAddress((void**)&kr_p,  g_kr);
    cudaGetSymbolAddress((void**)&idx_p, g_idx);

    cudaFuncSetAttribute(attn_kernel,
                         cudaFuncAttributeMaxDynamicSharedMemorySize,
                         ATTN_SMEM_BYTES);

    // 1) QKV projection: (25088x256) @ (768x256)^T + b -> g_qkv
    gemm_tf32_kernel<<<dim3(768 / GN, NPIX / GM), 256>>>(
        x, CC, qkv_w, qkv_b, qkv_p, 768, CC);

    // 2) region pooling
    pool_kernel<<<dim3(NREG, BATCH), CC>>>(qkv_p, qr_p, kr_p);

    // 3) coarse routing top-4
    route_kernel<<<dim3(NREG, BATCH), 64>>>(qr_p, kr_p, idx_p);

    // 4) sparse attention with fused lepe
    attn_kernel<<<dim3(NREG, NH, BATCH), 256, ATTN_SMEM_BYTES>>>(
        qkv_p, idx_p, lepe_w, lepe_b, ao_p);

    // 5) output projection -> d_out
    gemm_tf32_kernel<<<dim3(CC / GN, NPIX / GM), 256>>>(
        ao_p, CC, out_w, out_b, y, CC, CC);
}